// round 6
// baseline (speedup 1.0000x reference)
#include <cuda_runtime.h>
#include <cuda_bf16.h>
#include <cstdint>

// Problem constants
#define H 128
#define W 128
#define HW (H * W)          // 16384
#define C 32
#define KK 81               // 9x9
#define KS 9
#define DIL 2
#define PAD 8

#define PSTRIDE 144                  // padded row stride
#define PPLANE (PSTRIDE * PSTRIDE)   // 20736 floats per channel plane

// ---------------- device scratch (no allocations allowed) -------------------
__device__ __align__(16) float    g_k[KK * HW];        // guidance kernel [ij][p]
__device__ __align__(16) float    g_xpad[C * PPLANE];  // padded x
__device__ __align__(16) float    g_hpad[C * PPLANE];  // padded layer-1 output
// B fragments, prepacked per (ij, lane) in mma.sync m16n8k16 layout:
//   word index = ij*1024 + lane*32 + [hi:0 / lo:16] + s*8 + j*2 + r
__device__ __align__(16) uint32_t g_wf1[KK * 1024];
__device__ __align__(16) uint32_t g_wf2[KK * 1024];

// ---------------- helpers ---------------------------------------------------
__device__ __forceinline__ uint32_t cvt_bf2(float hi, float lo) {
    uint32_t r;
    asm("cvt.rn.bf16x2.f32 %0, %1, %2;" : "=r"(r) : "f"(hi), "f"(lo));
    return r;  // low half <- lo, high half <- hi
}

__device__ __forceinline__ void mma16816(float* d,
                                         uint32_t a0, uint32_t a1, uint32_t a2, uint32_t a3,
                                         uint32_t b0, uint32_t b1) {
    asm volatile(
        "mma.sync.aligned.m16n8k16.row.col.f32.bf16.bf16.f32 "
        "{%0,%1,%2,%3}, {%4,%5,%6,%7}, {%8,%9}, {%0,%1,%2,%3};"
        : "+f"(d[0]), "+f"(d[1]), "+f"(d[2]), "+f"(d[3])
        : "r"(a0), "r"(a1), "r"(a2), "r"(a3), "r"(b0), "r"(b1));
}

// ---------------- prep: weights -> per-lane B fragments (hi/lo bf16) --------
__global__ void prep_wf(const float* __restrict__ W1, const float* __restrict__ W2) {
    int tidg = blockIdx.x * blockDim.x + threadIdx.x;
    const int N = KK * 512;
    if (tidg >= 2 * N) return;
    int l = (tidg >= N);
    int e = l ? (tidg - N) : tidg;
    int ij = e >> 9;
    int widx = e & 511;
    int lane = widx >> 4;
    int q = widx & 15;
    int s = q >> 3, j = (q >> 1) & 3, r = q & 1;
    int g = lane >> 2, t = lane & 3;
    int o = 8 * j + g;
    int c0 = 16 * s + 2 * t + 8 * r;
    const float* Wsrc = l ? W2 : W1;
    float v0 = Wsrc[o * (C * KK) + c0 * KK + ij];
    float v1 = Wsrc[o * (C * KK) + (c0 + 1) * KK + ij];
    uint32_t h2 = cvt_bf2(v1, v0);
    float r0 = __uint_as_float(h2 << 16);
    float r1 = __uint_as_float(h2 & 0xffff0000u);
    uint32_t l2 = cvt_bf2(v1 - r1, v0 - r0);
    uint32_t* dst = (l ? g_wf2 : g_wf1) + ij * 1024 + lane * 32;
    dst[q] = h2;
    dst[16 + q] = l2;
}

// ---------------- pad x; zero hpad borders ----------------------------------
__global__ void pad_x(const float* __restrict__ x) {
    int t = blockIdx.x * blockDim.x + threadIdx.x;
    if (t >= C * PPLANE) return;
    int c = t / PPLANE;
    int rem = t - c * PPLANE;
    int r = rem / PSTRIDE;
    int col = rem - r * PSTRIDE;
    bool interior = (r >= PAD) && (r < PAD + H) && (col >= PAD) && (col < PAD + W);
    if (interior) {
        g_xpad[t] = x[c * HW + (r - PAD) * W + (col - PAD)];
    } else {
        g_xpad[t] = 0.f;
        g_hpad[t] = 0.f;
    }
}

// ---------------- guidance kernel (grid.y = 9 -> 9 ij per thread) -----------
__global__ void compute_k(const float* __restrict__ f) {
    int p = blockIdx.x * blockDim.x + threadIdx.x;
    int h = p >> 7;
    int w = p & 127;
    float fc[C];
#pragma unroll
    for (int c = 0; c < C; c++) fc[c] = __ldg(f + c * HW + p);
    float normc = 0.f;
#pragma unroll
    for (int c = 0; c < C; c++) normc = fmaf(fc[c], fc[c], normc);

    int ij0 = blockIdx.y * KS;
#pragma unroll 1
    for (int s = 0; s < KS; s++) {
        int ij = ij0 + s;
        int hh = h + (ij / KS) * DIL - PAD;
        int ww = w + (ij % KS) * DIL - PAD;
        float acc;
        if ((unsigned)hh < (unsigned)H && (unsigned)ww < (unsigned)W) {
            const float* fp = f + hh * W + ww;
            acc = 0.f;
#pragma unroll
            for (int c = 0; c < C; c++) {
                float d = __ldg(fp + c * HW) - fc[c];
                acc = fmaf(d, d, acc);
            }
        } else {
            acc = normc;
        }
        g_k[ij * HW + p] = __expf(-0.5f * acc);
    }
}

// ---------------- PAC conv via mma.sync (HMMA bf16, split hi/lo) ------------
// CTA = 64 px (half image row), 256 thr = 8 warps.
// Warps: mtile = wid>>1 (16 px each), role = wid&1.
//   role 0: hi-A x (Bhi + Blo), role 1: lo-A x Bhi. Partials summed in smem.
// Build: 256 thr = 64 px x 4 c-quarters.
#define ASLOT 10240                        // hi 5120 + lo 5120 (64 rows x 80 B)
#define SSLAB (3 * ASLOT)                  // 30720
#define SMEM_TOTAL (SSLAB + 32 * 80 * 4)   // + 10240 = 40960

__global__ void __launch_bounds__(256, 2)
pacmma(const float* __restrict__ xin,       // padded input planes (base)
       const uint32_t* __restrict__ wf,     // prepacked B fragments
       const float* __restrict__ bias,
       float* __restrict__ obase, int oplane, int orow) {
    extern __shared__ char smb[];
    float* slab = (float*)(smb + SSLAB);    // [c][0..79]

    int tid = threadIdx.x;
    int wid = tid >> 5;
    int lane = tid & 31;
    int g = lane >> 2, t = lane & 3;
    int h = blockIdx.x >> 1;
    int w0 = (blockIdx.x & 1) << 6;
    int px = tid & 63;                       // build: pixel
    int cq = tid >> 6;                       // build: c-quarter (0..3)
    int mtile = wid >> 1;                    // consume: 16-px tile 0..3
    int role = wid & 1;                      // 0: hi-A (2 passes), 1: lo-A

    float dacc[16];
#pragma unroll
    for (int i = 0; i < 16; i++) dacc[i] = 0.f;

    const float* kp = g_k + h * W + w0 + px;

#pragma unroll 1
    for (int di = 0; di < KS; di++) {
        {   // stage slab: 32 c x 80 floats of padded row (h + 2*di), cols [w0, w0+80)
            const float4* src = (const float4*)(xin + (size_t)(h + 2 * di) * PSTRIDE + w0);
            float4* dst = (float4*)slab;
#pragma unroll 1
            for (int i = tid; i < 32 * 20; i += 256) {
                int c = i / 20, q = i - c * 20;
                dst[i] = __ldg(src + (size_t)c * (PPLANE / 4) + q);
            }
        }
        __syncthreads();

#pragma unroll 1
        for (int b = 0; b < 3; b++) {
            // ---- build 3 A tiles (hi/lo) into slots 0..2 -------------------
#pragma unroll
            for (int s3 = 0; s3 < 3; s3++) {
                int dj = b * 3 + s3;
                int ij = di * KS + dj;
                float kv = __ldg(kp + (size_t)ij * HW);
                const float* zr = slab + px + 2 * dj;
                uint32_t hw[4], lw[4];
#pragma unroll
                for (int j = 0; j < 4; j++) {
                    float v0 = zr[(cq * 8 + 2 * j) * 80] * kv;
                    float v1 = zr[(cq * 8 + 2 * j + 1) * 80] * kv;
                    uint32_t h2 = cvt_bf2(v1, v0);
                    float r0 = __uint_as_float(h2 << 16);
                    float r1 = __uint_as_float(h2 & 0xffff0000u);
                    hw[j] = h2;
                    lw[j] = cvt_bf2(v1 - r1, v0 - r0);
                }
                char* a = smb + s3 * ASLOT + px * 80 + cq * 16;
                *(uint4*)a = make_uint4(hw[0], hw[1], hw[2], hw[3]);
                *(uint4*)(a + 5120) = make_uint4(lw[0], lw[1], lw[2], lw[3]);
            }
            __syncthreads();

            // ---- consume ---------------------------------------------------
#pragma unroll
            for (int s3 = 0; s3 < 3; s3++) {
                int ij = di * KS + b * 3 + s3;
                const uint4* wb = (const uint4*)(wf + (size_t)ij * 1024 + lane * 32);
                // A fragments for this warp's role (hi @0, lo @+5120)
                const char* ar0 = smb + s3 * ASLOT + role * 5120
                                + (16 * mtile + g) * 80 + t * 4;
                const char* ar1 = ar0 + 8 * 80;

                if (role == 0) {
                    uint4 u0 = __ldg(wb + 0), u1 = __ldg(wb + 1);
                    uint4 u2 = __ldg(wb + 2), u3 = __ldg(wb + 3);
                    uint4 v0 = __ldg(wb + 4), v1 = __ldg(wb + 5);
                    uint4 v2 = __ldg(wb + 6), v3 = __ldg(wb + 7);
                    uint32_t bh[16] = {u0.x,u0.y,u0.z,u0.w, u1.x,u1.y,u1.z,u1.w,
                                       u2.x,u2.y,u2.z,u2.w, u3.x,u3.y,u3.z,u3.w};
                    uint32_t bl[16] = {v0.x,v0.y,v0.z,v0.w, v1.x,v1.y,v1.z,v1.w,
                                       v2.x,v2.y,v2.z,v2.w, v3.x,v3.y,v3.z,v3.w};
#pragma unroll
                    for (int s = 0; s < 2; s++) {
                        uint32_t a0 = *(const uint32_t*)(ar0 + s * 32);
                        uint32_t a1 = *(const uint32_t*)(ar1 + s * 32);
                        uint32_t a2 = *(const uint32_t*)(ar0 + s * 32 + 16);
                        uint32_t a3 = *(const uint32_t*)(ar1 + s * 32 + 16);
#pragma unroll
                        for (int j = 0; j < 4; j++) {
                            mma16816(dacc + j * 4, a0, a1, a2, a3,
                                     bh[s * 8 + j * 2], bh[s * 8 + j * 2 + 1]);
                            mma16816(dacc + j * 4, a0, a1, a2, a3,
                                     bl[s * 8 + j * 2], bl[s * 8 + j * 2 + 1]);
                        }
                    }
                } else {
                    uint4 u0 = __ldg(wb + 0), u1 = __ldg(wb + 1);
                    uint4 u2 = __ldg(wb + 2), u3 = __ldg(wb + 3);
                    uint32_t bh[16] = {u0.x,u0.y,u0.z,u0.w, u1.x,u1.y,u1.z,u1.w,
                                       u2.x,u2.y,u2.z,u2.w, u3.x,u3.y,u3.z,u3.w};
#pragma unroll
                    for (int s = 0; s < 2; s++) {
                        uint32_t a0 = *(const uint32_t*)(ar0 + s * 32);
                        uint32_t a1 = *(const uint32_t*)(ar1 + s * 32);
                        uint32_t a2 = *(const uint32_t*)(ar0 + s * 32 + 16);
                        uint32_t a3 = *(const uint32_t*)(ar1 + s * 32 + 16);
#pragma unroll
                        for (int j = 0; j < 4; j++)
                            mma16816(dacc + j * 4, a0, a1, a2, a3,
                                     bh[s * 8 + j * 2], bh[s * 8 + j * 2 + 1]);
                    }
                }
            }
            __syncthreads();
        }
    }

    // ---- reduce role-1 partials into role-0, add bias, store ---------------
    if (role == 1) {
        float* sc = (float*)smb + mtile * 512 + lane;   // 2KB per mtile
#pragma unroll
        for (int i = 0; i < 16; i++) sc[i * 32] = dacc[i];
    }
    __syncthreads();
    if (role == 0) {
        const float* sc = (const float*)smb + mtile * 512 + lane;
#pragma unroll
        for (int i = 0; i < 16; i++) dacc[i] += sc[i * 32];

        float* ob = obase + (size_t)h * orow;
        int p0 = w0 + 16 * mtile + g, p1 = p0 + 8;
#pragma unroll
        for (int j = 0; j < 4; j++) {
            int o0 = 8 * j + 2 * t;
            float b0 = __ldg(bias + o0), b1 = __ldg(bias + o0 + 1);
            ob[(size_t)o0 * oplane + p0] = dacc[j * 4 + 0] + b0;
            ob[(size_t)(o0 + 1) * oplane + p0] = dacc[j * 4 + 1] + b1;
            ob[(size_t)o0 * oplane + p1] = dacc[j * 4 + 2] + b0;
            ob[(size_t)(o0 + 1) * oplane + p1] = dacc[j * 4 + 3] + b1;
        }
    }
}

// ---------------------------------------------------------------------------
extern "C" void kernel_launch(void* const* d_in, const int* in_sizes, int n_in,
                              void* d_out, int out_size) {
    const float* x = (const float*)d_in[0];
    const float* f = (const float*)d_in[1];
    const float* W1 = (const float*)d_in[2];
    const float* b1 = (const float*)d_in[3];
    const float* W2 = (const float*)d_in[4];
    const float* b2 = (const float*)d_in[5];
    float* out = (float*)d_out;

    float* xpad;   cudaGetSymbolAddress((void**)&xpad, g_xpad);
    float* hpad;   cudaGetSymbolAddress((void**)&hpad, g_hpad);
    uint32_t* wf1; cudaGetSymbolAddress((void**)&wf1, g_wf1);
    uint32_t* wf2; cudaGetSymbolAddress((void**)&wf2, g_wf2);

    cudaFuncSetAttribute(pacmma, cudaFuncAttributeMaxDynamicSharedMemorySize, SMEM_TOTAL);

    // 1. weights -> per-lane bf16 hi/lo fragments
    prep_wf<<<(2 * KK * 512 + 255) / 256, 256>>>(W1, W2);

    // 2. pad x; zero hpad borders
    pad_x<<<(C * PPLANE + 255) / 256, 256>>>(x);

    // 3. guidance kernel
    dim3 gk(HW / 256, KS);
    compute_k<<<gk, 256>>>(f);

    // 4. layer 1: xpad -> hpad interior
    pacmma<<<2 * H, 256, SMEM_TOTAL>>>(xpad, wf1, b1,
                                       hpad + PAD * PSTRIDE + PAD, PPLANE, PSTRIDE);

    // 5. layer 2: hpad -> out
    pacmma<<<2 * H, 256, SMEM_TOTAL>>>(hpad, wf2, b2, out, HW, W);
}

// round 7
// speedup vs baseline: 1.2182x; 1.2182x over previous
#include <cuda_runtime.h>
#include <cuda_bf16.h>
#include <cstdint>

// Problem constants
#define H 128
#define W 128
#define HW (H * W)          // 16384
#define CHW (32 * HW)       // 524288
#define C 32
#define KK 81               // 9x9
#define KS 9
#define DIL 2
#define PAD 8

#define PSTRIDE 144                  // padded row stride
#define PPLANE (PSTRIDE * PSTRIDE)   // 20736 floats per channel plane

// ---------------- device scratch (no allocations allowed) -------------------
__device__ __align__(16) float    g_k[KK * HW];        // guidance kernel [ij][p]
__device__ __align__(16) float    g_xpad[C * PPLANE];  // padded x
__device__ __align__(16) float    g_hpad[C * PPLANE];  // padded layer-1 output
__device__ __align__(16) float    g_part[3 * CHW];     // di-group partial sums
// B fragments, prepacked per (ij, lane) in mma.sync m16n8k16 layout:
//   word index = ij*1024 + lane*32 + [hi:0 / lo:16] + s*8 + j*2 + r
__device__ __align__(16) uint32_t g_wf1[KK * 1024];
__device__ __align__(16) uint32_t g_wf2[KK * 1024];

// ---------------- helpers ---------------------------------------------------
__device__ __forceinline__ uint32_t smem_u32(const void* p) {
    uint32_t a;
    asm("{ .reg .u64 t; cvta.to.shared.u64 t, %1; cvt.u32.u64 %0, t; }"
        : "=r"(a) : "l"(p));
    return a;
}
__device__ __forceinline__ uint32_t cvt_bf2(float hi, float lo) {
    uint32_t r;
    asm("cvt.rn.bf16x2.f32 %0, %1, %2;" : "=r"(r) : "f"(hi), "f"(lo));
    return r;  // low half <- lo, high half <- hi
}
__device__ __forceinline__ void mma16816(float* d,
                                         uint32_t a0, uint32_t a1, uint32_t a2, uint32_t a3,
                                         uint32_t b0, uint32_t b1) {
    asm volatile(
        "mma.sync.aligned.m16n8k16.row.col.f32.bf16.bf16.f32 "
        "{%0,%1,%2,%3}, {%4,%5,%6,%7}, {%8,%9}, {%0,%1,%2,%3};"
        : "+f"(d[0]), "+f"(d[1]), "+f"(d[2]), "+f"(d[3])
        : "r"(a0), "r"(a1), "r"(a2), "r"(a3), "r"(b0), "r"(b1));
}
__device__ __forceinline__ void ldm4(uint32_t* r, uint32_t addr) {
    asm volatile("ldmatrix.sync.aligned.m8n8.x4.shared.b16 {%0,%1,%2,%3}, [%4];"
                 : "=r"(r[0]), "=r"(r[1]), "=r"(r[2]), "=r"(r[3]) : "r"(addr));
}

// ---------------- prep: weights -> per-lane B fragments (hi/lo bf16) --------
__global__ void prep_wf(const float* __restrict__ W1, const float* __restrict__ W2) {
    int tidg = blockIdx.x * blockDim.x + threadIdx.x;
    const int N = KK * 512;
    if (tidg >= 2 * N) return;
    int l = (tidg >= N);
    int e = l ? (tidg - N) : tidg;
    int ij = e >> 9;
    int widx = e & 511;
    int lane = widx >> 4;
    int q = widx & 15;
    int s = q >> 3, j = (q >> 1) & 3, r = q & 1;
    int g = lane >> 2, t = lane & 3;
    int o = 8 * j + g;
    int c0 = 16 * s + 2 * t + 8 * r;
    const float* Wsrc = l ? W2 : W1;
    float v0 = Wsrc[o * (C * KK) + c0 * KK + ij];
    float v1 = Wsrc[o * (C * KK) + (c0 + 1) * KK + ij];
    uint32_t h2 = cvt_bf2(v1, v0);
    float r0 = __uint_as_float(h2 << 16);
    float r1 = __uint_as_float(h2 & 0xffff0000u);
    uint32_t l2 = cvt_bf2(v1 - r1, v0 - r0);
    uint32_t* dst = (l ? g_wf2 : g_wf1) + ij * 1024 + lane * 32;
    dst[q] = h2;
    dst[16 + q] = l2;
}

// ---------------- pad x; zero hpad borders ----------------------------------
__global__ void pad_x(const float* __restrict__ x) {
    int t = blockIdx.x * blockDim.x + threadIdx.x;
    if (t >= C * PPLANE) return;
    int c = t / PPLANE;
    int rem = t - c * PPLANE;
    int r = rem / PSTRIDE;
    int col = rem - r * PSTRIDE;
    bool interior = (r >= PAD) && (r < PAD + H) && (col >= PAD) && (col < PAD + W);
    if (interior) {
        g_xpad[t] = x[c * HW + (r - PAD) * W + (col - PAD)];
    } else {
        g_xpad[t] = 0.f;
        g_hpad[t] = 0.f;
    }
}

// ---------------- guidance kernel (grid.y = 9) ------------------------------
__global__ void compute_k(const float* __restrict__ f) {
    int p = blockIdx.x * blockDim.x + threadIdx.x;
    int h = p >> 7;
    int w = p & 127;
    float fc[C];
#pragma unroll
    for (int c = 0; c < C; c++) fc[c] = __ldg(f + c * HW + p);
    float normc = 0.f;
#pragma unroll
    for (int c = 0; c < C; c++) normc = fmaf(fc[c], fc[c], normc);

    int ij0 = blockIdx.y * KS;
#pragma unroll 1
    for (int s = 0; s < KS; s++) {
        int ij = ij0 + s;
        int hh = h + (ij / KS) * DIL - PAD;
        int ww = w + (ij % KS) * DIL - PAD;
        float acc;
        if ((unsigned)hh < (unsigned)H && (unsigned)ww < (unsigned)W) {
            const float* fp = f + hh * W + ww;
            acc = 0.f;
#pragma unroll
            for (int c = 0; c < C; c++) {
                float d = __ldg(fp + c * HW) - fc[c];
                acc = fmaf(d, d, acc);
            }
        } else {
            acc = normc;
        }
        g_k[ij * HW + p] = __expf(-0.5f * acc);
    }
}

// ---------------- PAC conv via mma.sync, di-split partials ------------------
// CTA: 128 thr (4 warps), 64 px, 27 ij (one di-group). grid (3, 2, 128).
// Per warp: one m16 tile, all 3 precision terms (24 HMMA/ij).
// Double-buffered A tiles; ONE __syncthreads per ij.
#define ASLOT 10240                 // one A buffer: hi 5120 + lo 5120 (80B rows)
#define SSLAB_OFF 20480             // slab: 32c x 80 floats = 10240 B
#define SMEM_TOTAL 30720

__global__ void __launch_bounds__(128, 4)
pacmma(const float* __restrict__ xin,       // padded input planes (base)
       const uint32_t* __restrict__ wf,     // prepacked B fragments
       float* __restrict__ part) {
    extern __shared__ char smb[];
    uint32_t sbase = smem_u32(smb);
    float* slab = (float*)(smb + SSLAB_OFF);

    int tid = threadIdx.x;
    int wid = tid >> 5;
    int lane = tid & 31;
    int g = lane >> 2, t = lane & 3;
    int grp = blockIdx.x;            // di group 0..2
    int w0 = blockIdx.y << 6;        // 0 or 64
    int h = blockIdx.z;
    int px = tid & 63;               // build: pixel
    int chalf = tid >> 6;            // build: c half (0/1)
    int mtile = wid;                 // consume: m16 tile

    // ldmatrix per-lane address base (row select + k-byte select)
    int rowsel = (lane & 7) + ((lane >> 3) & 1) * 8;
    int kbyte = ((lane >> 4) & 1) * 16;
    uint32_t abase = sbase + (uint32_t)(16 * mtile + rowsel) * 80 + kbyte;
    uint32_t bldbase = sbase + (uint32_t)px * 80 + chalf * 32;

    float dacc[16];
#pragma unroll
    for (int i = 0; i < 16; i++) dacc[i] = 0.f;

    const float* kp = g_k + h * W + w0 + px;

    // ---- build A(ij) into buffer buf (hi @0, lo @+5120) --------------------
    auto build = [&](int ij, int buf) {
        float kv = __ldg(kp + (size_t)ij * HW);
        int dj = ij - (ij / KS) * KS;
        const float* zr = slab + px + 2 * dj;
        uint32_t hw[8], lw[8];
#pragma unroll
        for (int j = 0; j < 8; j++) {
            float v0 = zr[(chalf * 16 + 2 * j) * 80] * kv;
            float v1 = zr[(chalf * 16 + 2 * j + 1) * 80] * kv;
            uint32_t h2 = cvt_bf2(v1, v0);
            float r0 = __uint_as_float(h2 << 16);
            float r1 = __uint_as_float(h2 & 0xffff0000u);
            hw[j] = h2;
            lw[j] = cvt_bf2(v1 - r1, v0 - r0);
        }
        uint32_t a = bldbase + buf * ASLOT;
        asm volatile("st.shared.v4.b32 [%0], {%1,%2,%3,%4};" ::
            "r"(a), "r"(hw[0]), "r"(hw[1]), "r"(hw[2]), "r"(hw[3]));
        asm volatile("st.shared.v4.b32 [%0], {%1,%2,%3,%4};" ::
            "r"(a + 16), "r"(hw[4]), "r"(hw[5]), "r"(hw[6]), "r"(hw[7]));
        asm volatile("st.shared.v4.b32 [%0], {%1,%2,%3,%4};" ::
            "r"(a + 5120), "r"(lw[0]), "r"(lw[1]), "r"(lw[2]), "r"(lw[3]));
        asm volatile("st.shared.v4.b32 [%0], {%1,%2,%3,%4};" ::
            "r"(a + 5136), "r"(lw[4]), "r"(lw[5]), "r"(lw[6]), "r"(lw[7]));
    };

    // ---- consume A(ij) from buffer buf -------------------------------------
    auto consume = [&](int ij, int buf) {
        const uint4* wb = (const uint4*)(wf + (size_t)ij * 1024 + lane * 32);
        uint4 u0 = __ldg(wb + 0), u1 = __ldg(wb + 1);
        uint4 u2 = __ldg(wb + 2), u3 = __ldg(wb + 3);
        uint4 v0 = __ldg(wb + 4), v1 = __ldg(wb + 5);
        uint4 v2 = __ldg(wb + 6), v3 = __ldg(wb + 7);

        uint32_t A0[4], A1[4], L0[4], L1[4];
        uint32_t ab = abase + buf * ASLOT;
        ldm4(A0, ab);                 // hi, c 0-15
        ldm4(A1, ab + 32);            // hi, c 16-31
        ldm4(L0, ab + 5120);          // lo, c 0-15
        ldm4(L1, ab + 5152);          // lo, c 16-31

        uint32_t bh[16] = {u0.x,u0.y,u0.z,u0.w, u1.x,u1.y,u1.z,u1.w,
                           u2.x,u2.y,u2.z,u2.w, u3.x,u3.y,u3.z,u3.w};
        uint32_t bl[16] = {v0.x,v0.y,v0.z,v0.w, v1.x,v1.y,v1.z,v1.w,
                           v2.x,v2.y,v2.z,v2.w, v3.x,v3.y,v3.z,v3.w};
#pragma unroll
        for (int s = 0; s < 2; s++) {
            uint32_t* A = s ? A1 : A0;
            uint32_t* L = s ? L1 : L0;
#pragma unroll
            for (int j = 0; j < 4; j++) {
                uint32_t b0 = bh[s * 8 + j * 2], b1 = bh[s * 8 + j * 2 + 1];
                mma16816(dacc + j * 4, A[0], A[1], A[2], A[3], b0, b1);
                mma16816(dacc + j * 4, L[0], L[1], L[2], L[3], b0, b1);
                mma16816(dacc + j * 4, A[0], A[1], A[2], A[3],
                         bl[s * 8 + j * 2], bl[s * 8 + j * 2 + 1]);
            }
        }
    };

#pragma unroll 1
    for (int dd = 0; dd < 3; dd++) {
        int di = grp * 3 + dd;
        __syncthreads();   // prior builders done with old slab
        {   // stage slab: 32 c x 80 floats of padded row (h + 2*di)
            const float4* src = (const float4*)(xin + (size_t)(h + 2 * di) * PSTRIDE + w0);
            float4* dst = (float4*)slab;
#pragma unroll 1
            for (int i = tid; i < 32 * 20; i += 128) {
                int c = i / 20, q = i - c * 20;
                dst[i] = __ldg(src + (size_t)c * (PPLANE / 4) + q);
            }
        }
        __syncthreads();
        build(di * KS, 0);
#pragma unroll 1
        for (int dj = 0; dj < KS; dj++) {
            __syncthreads();           // A(ij) visible; prev buffer free
            int ij = di * KS + dj;
            consume(ij, dj & 1);
            if (dj < KS - 1) build(ij + 1, (dj + 1) & 1);
        }
    }

    // ---- store partials (no bias) ------------------------------------------
    float* pp = part + (size_t)grp * CHW + h * W;
    int p0 = w0 + 16 * mtile + g, p1 = p0 + 8;
#pragma unroll
    for (int j = 0; j < 4; j++) {
        int o0 = 8 * j + 2 * t;
        pp[(size_t)o0 * HW + p0] = dacc[j * 4 + 0];
        pp[(size_t)(o0 + 1) * HW + p0] = dacc[j * 4 + 1];
        pp[(size_t)o0 * HW + p1] = dacc[j * 4 + 2];
        pp[(size_t)(o0 + 1) * HW + p1] = dacc[j * 4 + 3];
    }
}

// ---------------- reduce 3 partials + bias -> output ------------------------
__global__ void reduce_part(const float* __restrict__ bias,
                            float* __restrict__ out, int oplane, int orow) {
    int idx = blockIdx.x * 256 + threadIdx.x;   // over C*HW
    int o = idx >> 14;
    int p = idx & 16383;
    int hh = p >> 7, ww = p & 127;
    float v = __ldg(bias + o) + g_part[idx] + g_part[CHW + idx] + g_part[2 * CHW + idx];
    out[(size_t)o * oplane + hh * orow + ww] = v;
}

// ---------------------------------------------------------------------------
extern "C" void kernel_launch(void* const* d_in, const int* in_sizes, int n_in,
                              void* d_out, int out_size) {
    const float* x = (const float*)d_in[0];
    const float* f = (const float*)d_in[1];
    const float* W1 = (const float*)d_in[2];
    const float* b1 = (const float*)d_in[3];
    const float* W2 = (const float*)d_in[4];
    const float* b2 = (const float*)d_in[5];
    float* out = (float*)d_out;

    float* xpad;   cudaGetSymbolAddress((void**)&xpad, g_xpad);
    float* hpad;   cudaGetSymbolAddress((void**)&hpad, g_hpad);
    float* part;   cudaGetSymbolAddress((void**)&part, g_part);
    uint32_t* wf1; cudaGetSymbolAddress((void**)&wf1, g_wf1);
    uint32_t* wf2; cudaGetSymbolAddress((void**)&wf2, g_wf2);

    // 1. weights -> per-lane bf16 hi/lo fragments
    prep_wf<<<(2 * KK * 512 + 255) / 256, 256>>>(W1, W2);

    // 2. pad x; zero hpad borders
    pad_x<<<(C * PPLANE + 255) / 256, 256>>>(x);

    // 3. guidance kernel
    dim3 gk(HW / 256, KS);
    compute_k<<<gk, 256>>>(f);

    dim3 gp(3, 2, H);   // (di-group, half-row, row)

    // 4. layer 1 partials + reduce into hpad interior
    pacmma<<<gp, 128, SMEM_TOTAL>>>(xpad, wf1, part);
    reduce_part<<<CHW / 256, 256>>>(b1, hpad + PAD * PSTRIDE + PAD, PPLANE, PSTRIDE);

    // 5. layer 2 partials + reduce into out
    pacmma<<<gp, 128, SMEM_TOTAL>>>(hpad, wf2, part);
    reduce_part<<<CHW / 256, 256>>>(b2, out, HW, W);
}

// round 8
// speedup vs baseline: 3.9060x; 3.2065x over previous
#include <cuda_runtime.h>
#include <cuda_bf16.h>
#include <cstdint>

// Problem constants
#define H 128
#define W 128
#define HW (H * W)          // 16384
#define CHW (32 * HW)       // 524288
#define C 32
#define KK 81               // 9x9
#define KS 9
#define DIL 2
#define PAD 8

#define PSTRIDE 144                  // padded row stride
#define PPLANE (PSTRIDE * PSTRIDE)   // 20736 floats per channel plane

// T buffer geometry (transposed bf16 slab): row = padded col (0..143),
// entry = channel c (0..31), 2B each, row stride 80B (16B pad, conflict-free).
#define TSTRIDE 80
#define TLO (144 * TSTRIDE)          // 11520: lo plane offset
#define SMEM_TOTAL (2 * TLO)         // 23040

// ---------------- device scratch (no allocations allowed) -------------------
__device__ __align__(16) float    g_k[KK * HW];        // guidance kernel [ij][p]
__device__ __align__(16) float    g_xpad[C * PPLANE];  // padded x
__device__ __align__(16) float    g_hpad[C * PPLANE];  // padded layer-1 output
__device__ __align__(16) float    g_part[3 * CHW];     // di-group partial sums
// B fragments, coalesced layout: word = ij*1024 + w*32 + lane,
//   w 0..15 = hi frags, w 16..31 = lo frags
__device__ __align__(16) uint32_t g_wf1[KK * 1024];
__device__ __align__(16) uint32_t g_wf2[KK * 1024];

// ---------------- helpers ---------------------------------------------------
__device__ __forceinline__ uint32_t cvt_bf2(float hi, float lo) {
    uint32_t r;
    asm("cvt.rn.bf16x2.f32 %0, %1, %2;" : "=r"(r) : "f"(hi), "f"(lo));
    return r;  // low half <- lo, high half <- hi
}
__device__ __forceinline__ void mma_acc(float* d,
                                        uint32_t a0, uint32_t a1, uint32_t a2, uint32_t a3,
                                        uint32_t b0, uint32_t b1) {
    asm volatile(
        "mma.sync.aligned.m16n8k16.row.col.f32.bf16.bf16.f32 "
        "{%0,%1,%2,%3}, {%4,%5,%6,%7}, {%8,%9}, {%0,%1,%2,%3};"
        : "+f"(d[0]), "+f"(d[1]), "+f"(d[2]), "+f"(d[3])
        : "r"(a0), "r"(a1), "r"(a2), "r"(a3), "r"(b0), "r"(b1));
}
__device__ __forceinline__ void mma_init(float* d,
                                         uint32_t a0, uint32_t a1, uint32_t a2, uint32_t a3,
                                         uint32_t b0, uint32_t b1) {
    asm volatile(
        "mma.sync.aligned.m16n8k16.row.col.f32.bf16.bf16.f32 "
        "{%0,%1,%2,%3}, {%4,%5,%6,%7}, {%8,%9}, {%10,%11,%12,%13};"
        : "=f"(d[0]), "=f"(d[1]), "=f"(d[2]), "=f"(d[3])
        : "r"(a0), "r"(a1), "r"(a2), "r"(a3), "r"(b0), "r"(b1),
          "f"(0.f), "f"(0.f), "f"(0.f), "f"(0.f));
}

// ---------------- prep: weights -> coalesced B fragments (hi/lo bf16) -------
__global__ void prep_wf(const float* __restrict__ W1, const float* __restrict__ W2) {
    int tidg = blockIdx.x * blockDim.x + threadIdx.x;
    const int N = KK * 512;
    if (tidg >= 2 * N) return;
    int l = (tidg >= N);
    int e = l ? (tidg - N) : tidg;
    int ij = e >> 9;
    int widx = e & 511;
    int lane = widx >> 4;
    int q = widx & 15;
    int s = q >> 3, j = (q >> 1) & 3, r = q & 1;
    int g = lane >> 2, t = lane & 3;
    int o = 8 * j + g;
    int c0 = 16 * s + 2 * t + 8 * r;
    const float* Wsrc = l ? W2 : W1;
    float v0 = Wsrc[o * (C * KK) + c0 * KK + ij];
    float v1 = Wsrc[o * (C * KK) + (c0 + 1) * KK + ij];
    uint32_t h2 = cvt_bf2(v1, v0);
    float r0 = __uint_as_float(h2 << 16);
    float r1 = __uint_as_float(h2 & 0xffff0000u);
    uint32_t l2 = cvt_bf2(v1 - r1, v0 - r0);
    uint32_t* dst = (l ? g_wf2 : g_wf1) + ij * 1024;
    dst[q * 32 + lane] = h2;
    dst[(16 + q) * 32 + lane] = l2;
}

// ---------------- pad x; zero hpad borders ----------------------------------
__global__ void pad_x(const float* __restrict__ x) {
    int t = blockIdx.x * blockDim.x + threadIdx.x;
    if (t >= C * PPLANE) return;
    int c = t / PPLANE;
    int rem = t - c * PPLANE;
    int r = rem / PSTRIDE;
    int col = rem - r * PSTRIDE;
    bool interior = (r >= PAD) && (r < PAD + H) && (col >= PAD) && (col < PAD + W);
    if (interior) {
        g_xpad[t] = x[c * HW + (r - PAD) * W + (col - PAD)];
    } else {
        g_xpad[t] = 0.f;
        g_hpad[t] = 0.f;
    }
}

// ---------------- guidance kernel (grid.y = 9) ------------------------------
__global__ void compute_k(const float* __restrict__ f) {
    int p = blockIdx.x * blockDim.x + threadIdx.x;
    int h = p >> 7;
    int w = p & 127;
    float fc[C];
#pragma unroll
    for (int c = 0; c < C; c++) fc[c] = __ldg(f + c * HW + p);
    float normc = 0.f;
#pragma unroll
    for (int c = 0; c < C; c++) normc = fmaf(fc[c], fc[c], normc);

    int ij0 = blockIdx.y * KS;
#pragma unroll 1
    for (int s = 0; s < KS; s++) {
        int ij = ij0 + s;
        int hh = h + (ij / KS) * DIL - PAD;
        int ww = w + (ij % KS) * DIL - PAD;
        float acc;
        if ((unsigned)hh < (unsigned)H && (unsigned)ww < (unsigned)W) {
            const float* fp = f + hh * W + ww;
            acc = 0.f;
#pragma unroll
            for (int c = 0; c < C; c++) {
                float d = __ldg(fp + c * HW) - fc[c];
                acc = fmaf(d, d, acc);
            }
        } else {
            acc = normc;
        }
        g_k[ij * HW + p] = __expf(-0.5f * acc);
    }
}

// ---------------- PAC conv: kv-hoisted MMA, per-di transposed bf16 T --------
// CTA: 128 thr (4 warps), full 128-px row, one di-group (3 di). grid (3, 128).
// Per warp: 2 m16 tiles. Per ij: V = Xshift * W[ij] (3-term bf16 split MMA),
// then dacc += kv[px] * V (f32). T built once per di; A(dj) = shifted LDS view.
__global__ void __launch_bounds__(128, 4)
pacmma(const float* __restrict__ xin,       // padded input planes (base)
       const uint32_t* __restrict__ wf,     // coalesced B fragments
       float* __restrict__ part) {
    extern __shared__ char Tb[];            // [144 rows x 80B] hi, + lo @ TLO

    int tid = threadIdx.x;
    int wid = tid >> 5;
    int lane = tid & 31;
    int gr = lane >> 2, t4 = lane & 3;
    int grp = blockIdx.x;                   // di group 0..2
    int h = blockIdx.y;

    float dacc[32];
#pragma unroll
    for (int i = 0; i < 32; i++) dacc[i] = 0.f;

    const float* kprow = g_k + h * W;

#pragma unroll 1
    for (int dd = 0; dd < 3; dd++) {
        int di = grp * 3 + dd;
        int prow = h + 2 * di;
        __syncthreads();
        // ---- build T: bf16 hi/lo transpose of x[32c][row prow][col 0..143] --
#pragma unroll
        for (int i = 0; i < 5; i++) {
            int task = tid + i * 128;       // (coct 0..3) x (col 0..159)
            int coct = task / 160;
            int col = task - coct * 160;
            if (col < 144) {
                const float* xp = xin + (size_t)(coct * 8) * PPLANE
                                + (size_t)prow * PSTRIDE + col;
                float v[8];
#pragma unroll
                for (int j = 0; j < 8; j++) v[j] = __ldg(xp + j * PPLANE);
                uint32_t hw[4], lw[4];
#pragma unroll
                for (int j = 0; j < 4; j++) {
                    uint32_t h2 = cvt_bf2(v[2 * j + 1], v[2 * j]);
                    float r0 = __uint_as_float(h2 << 16);
                    float r1 = __uint_as_float(h2 & 0xffff0000u);
                    hw[j] = h2;
                    lw[j] = cvt_bf2(v[2 * j + 1] - r1, v[2 * j] - r0);
                }
                char* dst = Tb + col * TSTRIDE + coct * 16;
                *(uint4*)dst = make_uint4(hw[0], hw[1], hw[2], hw[3]);
                *(uint4*)(dst + TLO) = make_uint4(lw[0], lw[1], lw[2], lw[3]);
            }
        }
        __syncthreads();

        // ---- consume 9 dj ---------------------------------------------------
        const float* kp = kprow + (size_t)(di * KS) * HW;
#pragma unroll 1
        for (int dj = 0; dj < KS; dj++) {
            int ij = di * KS + dj;
            // B fragments: coalesced LDG.32, L1-hot (shared by all warps/CTAs)
            const uint32_t* wp = wf + (size_t)ij * 1024 + lane;
            uint32_t bh[16], bl[16];
#pragma unroll
            for (int q = 0; q < 16; q++) bh[q] = __ldg(wp + q * 32);
#pragma unroll
            for (int q = 0; q < 16; q++) bl[q] = __ldg(wp + (16 + q) * 32);

#pragma unroll
            for (int mt = 0; mt < 2; mt++) {
                int mtile = wid * 2 + mt;
                int px0 = 16 * mtile + gr;
                float kv0 = __ldg(kp + px0);
                float kv1 = __ldg(kp + px0 + 8);
                const char* ta = Tb + (px0 + 2 * dj) * TSTRIDE + 4 * t4;

                float V[16];
#pragma unroll
                for (int s = 0; s < 2; s++) {
                    uint32_t a0 = *(const uint32_t*)(ta + 32 * s);
                    uint32_t a1 = *(const uint32_t*)(ta + 32 * s + 8 * TSTRIDE);
                    uint32_t a2 = *(const uint32_t*)(ta + 32 * s + 16);
                    uint32_t a3 = *(const uint32_t*)(ta + 32 * s + 8 * TSTRIDE + 16);
                    uint32_t l0 = *(const uint32_t*)(ta + TLO + 32 * s);
                    uint32_t l1 = *(const uint32_t*)(ta + TLO + 32 * s + 8 * TSTRIDE);
                    uint32_t l2 = *(const uint32_t*)(ta + TLO + 32 * s + 16);
                    uint32_t l3 = *(const uint32_t*)(ta + TLO + 32 * s + 8 * TSTRIDE + 16);
#pragma unroll
                    for (int j = 0; j < 4; j++) {
                        uint32_t b0 = bh[s * 8 + j * 2], b1 = bh[s * 8 + j * 2 + 1];
                        if (s == 0) mma_init(V + j * 4, a0, a1, a2, a3, b0, b1);
                        else        mma_acc(V + j * 4, a0, a1, a2, a3, b0, b1);
                        mma_acc(V + j * 4, l0, l1, l2, l3, b0, b1);
                        mma_acc(V + j * 4, a0, a1, a2, a3,
                                bl[s * 8 + j * 2], bl[s * 8 + j * 2 + 1]);
                    }
                }
                float* dm = dacc + mt * 16;
#pragma unroll
                for (int j = 0; j < 4; j++) {
                    dm[j * 4 + 0] = fmaf(kv0, V[j * 4 + 0], dm[j * 4 + 0]);
                    dm[j * 4 + 1] = fmaf(kv0, V[j * 4 + 1], dm[j * 4 + 1]);
                    dm[j * 4 + 2] = fmaf(kv1, V[j * 4 + 2], dm[j * 4 + 2]);
                    dm[j * 4 + 3] = fmaf(kv1, V[j * 4 + 3], dm[j * 4 + 3]);
                }
            }
            kp += HW;
        }
    }

    // ---- store partials -----------------------------------------------------
    float* pp = g_part + (size_t)grp * CHW + h * W;
#pragma unroll
    for (int mt = 0; mt < 2; mt++) {
        int p0 = 16 * (wid * 2 + mt) + gr, p1 = p0 + 8;
        const float* dm = dacc + mt * 16;
#pragma unroll
        for (int j = 0; j < 4; j++) {
            int o0 = 8 * j + 2 * t4;
            pp[(size_t)o0 * HW + p0] = dm[j * 4 + 0];
            pp[(size_t)(o0 + 1) * HW + p0] = dm[j * 4 + 1];
            pp[(size_t)o0 * HW + p1] = dm[j * 4 + 2];
            pp[(size_t)(o0 + 1) * HW + p1] = dm[j * 4 + 3];
        }
    }
    (void)part;
}

// ---------------- reduce 3 partials + bias -> output ------------------------
__global__ void reduce_part(const float* __restrict__ bias,
                            float* __restrict__ out, int oplane, int orow) {
    int idx = blockIdx.x * 256 + threadIdx.x;   // over C*HW
    int o = idx >> 14;
    int p = idx & 16383;
    int hh = p >> 7, ww = p & 127;
    float v = __ldg(bias + o) + g_part[idx] + g_part[CHW + idx] + g_part[2 * CHW + idx];
    out[(size_t)o * oplane + hh * orow + ww] = v;
}

// ---------------------------------------------------------------------------
extern "C" void kernel_launch(void* const* d_in, const int* in_sizes, int n_in,
                              void* d_out, int out_size) {
    const float* x = (const float*)d_in[0];
    const float* f = (const float*)d_in[1];
    const float* W1 = (const float*)d_in[2];
    const float* b1 = (const float*)d_in[3];
    const float* W2 = (const float*)d_in[4];
    const float* b2 = (const float*)d_in[5];
    float* out = (float*)d_out;

    float* xpad;   cudaGetSymbolAddress((void**)&xpad, g_xpad);
    float* hpad;   cudaGetSymbolAddress((void**)&hpad, g_hpad);
    float* part;   cudaGetSymbolAddress((void**)&part, g_part);
    uint32_t* wf1; cudaGetSymbolAddress((void**)&wf1, g_wf1);
    uint32_t* wf2; cudaGetSymbolAddress((void**)&wf2, g_wf2);

    cudaFuncSetAttribute(pacmma, cudaFuncAttributeMaxDynamicSharedMemorySize, SMEM_TOTAL);

    // 1. weights -> coalesced bf16 hi/lo fragments
    prep_wf<<<(2 * KK * 512 + 255) / 256, 256>>>(W1, W2);

    // 2. pad x; zero hpad borders
    pad_x<<<(C * PPLANE + 255) / 256, 256>>>(x);

    // 3. guidance kernel
    dim3 gk(HW / 256, KS);
    compute_k<<<gk, 256>>>(f);

    dim3 gp(3, H);   // (di-group, row)

    // 4. layer 1 partials + reduce into hpad interior
    pacmma<<<gp, 128, SMEM_TOTAL>>>(xpad, wf1, part);
    reduce_part<<<CHW / 256, 256>>>(b1, hpad + PAD * PSTRIDE + PAD, PPLANE, PSTRIDE);

    // 5. layer 2 partials + reduce into out
    pacmma<<<gp, 128, SMEM_TOTAL>>>(hpad, wf2, part);
    reduce_part<<<CHW / 256, 256>>>(b2, out, HW, W);
}

// round 9
// speedup vs baseline: 4.6519x; 1.1910x over previous
#include <cuda_runtime.h>
#include <cuda_bf16.h>
#include <cstdint>

// Problem constants
#define H 128
#define W 128
#define HW (H * W)          // 16384
#define CHW (32 * HW)       // 524288
#define C 32
#define KK 81               // 9x9
#define KS 9
#define DIL 2
#define PAD 8

#define PSTRIDE 144                  // padded row stride
#define PPLANE (PSTRIDE * PSTRIDE)   // 20736 floats per channel plane

// T buffer geometry (transposed bf16 slab): row = padded col (0..143),
// entry = channel c (0..31), 2B each, row stride 80B (conflict-free).
#define TSTRIDE 80
#define TLO (144 * TSTRIDE)          // 11520: lo plane offset
#define SMEM_TOTAL (2 * TLO)         // 23040

// ---------------- device scratch (no allocations allowed) -------------------
__device__ __align__(16) float    g_k[KK * HW];        // guidance kernel [ij][p]
__device__ __align__(16) float    g_xpad[C * PPLANE];  // padded x
__device__ __align__(16) float    g_hpad[C * PPLANE];  // padded layer-1 output
__device__ __align__(16) float    g_part[9 * CHW];     // per-di partial sums
// B fragments, pair-interleaved for LDG.64:
//   word = ij*1024 + qq*64 + lane*2 + r  holds frag word (2*qq + r);
//   qq 0..7 -> hi frags 0..15, qq 8..15 -> lo frags 0..15
__device__ __align__(16) uint32_t g_wf1[KK * 1024];
__device__ __align__(16) uint32_t g_wf2[KK * 1024];

// ---------------- helpers ---------------------------------------------------
__device__ __forceinline__ uint32_t cvt_bf2(float hi, float lo) {
    uint32_t r;
    asm("cvt.rn.bf16x2.f32 %0, %1, %2;" : "=r"(r) : "f"(hi), "f"(lo));
    return r;  // low half <- lo, high half <- hi
}
__device__ __forceinline__ void mma_acc(float* d,
                                        uint32_t a0, uint32_t a1, uint32_t a2, uint32_t a3,
                                        uint32_t b0, uint32_t b1) {
    asm volatile(
        "mma.sync.aligned.m16n8k16.row.col.f32.bf16.bf16.f32 "
        "{%0,%1,%2,%3}, {%4,%5,%6,%7}, {%8,%9}, {%0,%1,%2,%3};"
        : "+f"(d[0]), "+f"(d[1]), "+f"(d[2]), "+f"(d[3])
        : "r"(a0), "r"(a1), "r"(a2), "r"(a3), "r"(b0), "r"(b1));
}
__device__ __forceinline__ void mma_init(float* d,
                                         uint32_t a0, uint32_t a1, uint32_t a2, uint32_t a3,
                                         uint32_t b0, uint32_t b1) {
    asm volatile(
        "mma.sync.aligned.m16n8k16.row.col.f32.bf16.bf16.f32 "
        "{%0,%1,%2,%3}, {%4,%5,%6,%7}, {%8,%9}, {%10,%11,%12,%13};"
        : "=f"(d[0]), "=f"(d[1]), "=f"(d[2]), "=f"(d[3])
        : "r"(a0), "r"(a1), "r"(a2), "r"(a3), "r"(b0), "r"(b1),
          "f"(0.f), "f"(0.f), "f"(0.f), "f"(0.f));
}

// ---------------- prep: weights -> pair-interleaved B fragments -------------
__global__ void prep_wf(const float* __restrict__ W1, const float* __restrict__ W2) {
    int tidg = blockIdx.x * blockDim.x + threadIdx.x;
    const int N = KK * 512;
    if (tidg >= 2 * N) return;
    int l = (tidg >= N);
    int e = l ? (tidg - N) : tidg;
    int ij = e >> 9;
    int widx = e & 511;
    int lane = widx >> 4;
    int q = widx & 15;                 // frag word index 0..15
    int s = q >> 3, j = (q >> 1) & 3, r = q & 1;
    int g = lane >> 2, t = lane & 3;
    int o = 8 * j + g;
    int c0 = 16 * s + 2 * t + 8 * r;
    const float* Wsrc = l ? W2 : W1;
    float v0 = Wsrc[o * (C * KK) + c0 * KK + ij];
    float v1 = Wsrc[o * (C * KK) + (c0 + 1) * KK + ij];
    uint32_t h2 = cvt_bf2(v1, v0);
    float r0 = __uint_as_float(h2 << 16);
    float r1 = __uint_as_float(h2 & 0xffff0000u);
    uint32_t l2 = cvt_bf2(v1 - r1, v0 - r0);
    uint32_t* dst = (l ? g_wf2 : g_wf1) + ij * 1024;
    // pair-interleave: frag word f at qq=f>>1, r=f&1 -> qq*64 + lane*2 + r
    dst[(q >> 1) * 64 + lane * 2 + (q & 1)] = h2;            // hi: f = q
    dst[(8 + (q >> 1)) * 64 + lane * 2 + (q & 1)] = l2;      // lo: f = q (in lo bank)
}

// ---------------- pad x; zero hpad borders ----------------------------------
__global__ void pad_x(const float* __restrict__ x) {
    int t = blockIdx.x * blockDim.x + threadIdx.x;
    if (t >= C * PPLANE) return;
    int c = t / PPLANE;
    int rem = t - c * PPLANE;
    int r = rem / PSTRIDE;
    int col = rem - r * PSTRIDE;
    bool interior = (r >= PAD) && (r < PAD + H) && (col >= PAD) && (col < PAD + W);
    if (interior) {
        g_xpad[t] = x[c * HW + (r - PAD) * W + (col - PAD)];
    } else {
        g_xpad[t] = 0.f;
        g_hpad[t] = 0.f;
    }
}

// ---------------- guidance kernel (grid.y = 9) ------------------------------
__global__ void compute_k(const float* __restrict__ f) {
    int p = blockIdx.x * blockDim.x + threadIdx.x;
    int h = p >> 7;
    int w = p & 127;
    float fc[C];
#pragma unroll
    for (int c = 0; c < C; c++) fc[c] = __ldg(f + c * HW + p);
    float normc = 0.f;
#pragma unroll
    for (int c = 0; c < C; c++) normc = fmaf(fc[c], fc[c], normc);

    int ij0 = blockIdx.y * KS;
#pragma unroll 1
    for (int s = 0; s < KS; s++) {
        int ij = ij0 + s;
        int hh = h + (ij / KS) * DIL - PAD;
        int ww = w + (ij % KS) * DIL - PAD;
        float acc;
        if ((unsigned)hh < (unsigned)H && (unsigned)ww < (unsigned)W) {
            const float* fp = f + hh * W + ww;
            acc = 0.f;
#pragma unroll
            for (int c = 0; c < C; c++) {
                float d = __ldg(fp + c * HW) - fc[c];
                acc = fmaf(d, d, acc);
            }
        } else {
            acc = normc;
        }
        g_k[ij * HW + p] = __expf(-0.5f * acc);
    }
}

// ---------------- PAC conv: kv-hoisted MMA, one di per CTA ------------------
// CTA: 128 thr (4 warps), full 128-px row, ONE di (9 dj). grid (9, 128).
// Per warp: 2 m16 tiles. Per ij: V = Xshift * W[ij] (3-term bf16 split MMA),
// then dacc += kv[px] * V (f32). T built once; single barrier per CTA.
__global__ void __launch_bounds__(128, 4)
pacmma(const float* __restrict__ xin,       // padded input planes (base)
       const uint32_t* __restrict__ wf) {   // pair-interleaved B fragments
    extern __shared__ char Tb[];            // [144 rows x 80B] hi, + lo @ TLO

    int tid = threadIdx.x;
    int wid = tid >> 5;
    int lane = tid & 31;
    int gr = lane >> 2, t4 = lane & 3;
    int di = blockIdx.x;                    // 0..8
    int h = blockIdx.y;

    float dacc[32];
#pragma unroll
    for (int i = 0; i < 32; i++) dacc[i] = 0.f;

    // ---- build T: bf16 hi/lo transpose of x[32c][row h+2di][col 0..143] ----
    {
        int prow = h + 2 * di;
#pragma unroll
        for (int i = 0; i < 5; i++) {
            int task = tid + i * 128;       // (coct 0..3) x (col 0..159)
            int coct = task / 160;
            int col = task - coct * 160;
            if (col < 144) {
                const float* xp = xin + (size_t)(coct * 8) * PPLANE
                                + (size_t)prow * PSTRIDE + col;
                float v[8];
#pragma unroll
                for (int j = 0; j < 8; j++) v[j] = __ldg(xp + j * PPLANE);
                uint32_t hw[4], lw[4];
#pragma unroll
                for (int j = 0; j < 4; j++) {
                    uint32_t h2 = cvt_bf2(v[2 * j + 1], v[2 * j]);
                    float r0 = __uint_as_float(h2 << 16);
                    float r1 = __uint_as_float(h2 & 0xffff0000u);
                    hw[j] = h2;
                    lw[j] = cvt_bf2(v[2 * j + 1] - r1, v[2 * j] - r0);
                }
                char* dst = Tb + col * TSTRIDE + coct * 16;
                *(uint4*)dst = make_uint4(hw[0], hw[1], hw[2], hw[3]);
                *(uint4*)(dst + TLO) = make_uint4(lw[0], lw[1], lw[2], lw[3]);
            }
        }
    }
    __syncthreads();

    // ---- consume 9 dj -------------------------------------------------------
    const float* kp = g_k + h * W + (size_t)(di * KS) * HW;
#pragma unroll 1
    for (int dj = 0; dj < KS; dj++) {
        int ij = di * KS + dj;
        // B fragments: 16 coalesced LDG.64 (pair-interleaved layout)
        const uint2* wp = (const uint2*)(wf + (size_t)ij * 1024) + lane;
        uint32_t bh[16], bl[16];
#pragma unroll
        for (int qq = 0; qq < 8; qq++) {
            uint2 u = __ldg(wp + qq * 32);
            bh[2 * qq] = u.x; bh[2 * qq + 1] = u.y;
        }
#pragma unroll
        for (int qq = 0; qq < 8; qq++) {
            uint2 u = __ldg(wp + (8 + qq) * 32);
            bl[2 * qq] = u.x; bl[2 * qq + 1] = u.y;
        }

#pragma unroll
        for (int mt = 0; mt < 2; mt++) {
            int mtile = wid * 2 + mt;
            int px0 = 16 * mtile + gr;
            float kv0 = __ldg(kp + px0);
            float kv1 = __ldg(kp + px0 + 8);
            const char* ta = Tb + (px0 + 2 * dj) * TSTRIDE + 4 * t4;

            float V[16];
#pragma unroll
            for (int s = 0; s < 2; s++) {
                uint32_t a0 = *(const uint32_t*)(ta + 32 * s);
                uint32_t a1 = *(const uint32_t*)(ta + 32 * s + 8 * TSTRIDE);
                uint32_t a2 = *(const uint32_t*)(ta + 32 * s + 16);
                uint32_t a3 = *(const uint32_t*)(ta + 32 * s + 8 * TSTRIDE + 16);
                uint32_t l0 = *(const uint32_t*)(ta + TLO + 32 * s);
                uint32_t l1 = *(const uint32_t*)(ta + TLO + 32 * s + 8 * TSTRIDE);
                uint32_t l2 = *(const uint32_t*)(ta + TLO + 32 * s + 16);
                uint32_t l3 = *(const uint32_t*)(ta + TLO + 32 * s + 8 * TSTRIDE + 16);
#pragma unroll
                for (int j = 0; j < 4; j++) {
                    uint32_t b0 = bh[s * 8 + j * 2], b1 = bh[s * 8 + j * 2 + 1];
                    if (s == 0) mma_init(V + j * 4, a0, a1, a2, a3, b0, b1);
                    else        mma_acc(V + j * 4, a0, a1, a2, a3, b0, b1);
                    mma_acc(V + j * 4, l0, l1, l2, l3, b0, b1);
                    mma_acc(V + j * 4, a0, a1, a2, a3,
                            bl[s * 8 + j * 2], bl[s * 8 + j * 2 + 1]);
                }
            }
            float* dm = dacc + mt * 16;
#pragma unroll
            for (int j = 0; j < 4; j++) {
                dm[j * 4 + 0] = fmaf(kv0, V[j * 4 + 0], dm[j * 4 + 0]);
                dm[j * 4 + 1] = fmaf(kv0, V[j * 4 + 1], dm[j * 4 + 1]);
                dm[j * 4 + 2] = fmaf(kv1, V[j * 4 + 2], dm[j * 4 + 2]);
                dm[j * 4 + 3] = fmaf(kv1, V[j * 4 + 3], dm[j * 4 + 3]);
            }
        }
        kp += HW;
    }

    // ---- store partials -----------------------------------------------------
    float* pp = g_part + (size_t)di * CHW + h * W;
#pragma unroll
    for (int mt = 0; mt < 2; mt++) {
        int p0 = 16 * (wid * 2 + mt) + gr, p1 = p0 + 8;
        const float* dm = dacc + mt * 16;
#pragma unroll
        for (int j = 0; j < 4; j++) {
            int o0 = 8 * j + 2 * t4;
            pp[(size_t)o0 * HW + p0] = dm[j * 4 + 0];
            pp[(size_t)(o0 + 1) * HW + p0] = dm[j * 4 + 1];
            pp[(size_t)o0 * HW + p1] = dm[j * 4 + 2];
            pp[(size_t)(o0 + 1) * HW + p1] = dm[j * 4 + 3];
        }
    }
}

// ---------------- reduce 9 partials + bias -> output ------------------------
__global__ void reduce_part(const float* __restrict__ bias,
                            float* __restrict__ out, int oplane, int orow) {
    int idx = blockIdx.x * 256 + threadIdx.x;   // over C*HW
    int o = idx >> 14;
    int p = idx & 16383;
    int hh = p >> 7, ww = p & 127;
    float v = __ldg(bias + o);
#pragma unroll
    for (int g = 0; g < 9; g++) v += g_part[(size_t)g * CHW + idx];
    out[(size_t)o * oplane + hh * orow + ww] = v;
}

// ---------------------------------------------------------------------------
extern "C" void kernel_launch(void* const* d_in, const int* in_sizes, int n_in,
                              void* d_out, int out_size) {
    const float* x = (const float*)d_in[0];
    const float* f = (const float*)d_in[1];
    const float* W1 = (const float*)d_in[2];
    const float* b1 = (const float*)d_in[3];
    const float* W2 = (const float*)d_in[4];
    const float* b2 = (const float*)d_in[5];
    float* out = (float*)d_out;

    float* xpad;   cudaGetSymbolAddress((void**)&xpad, g_xpad);
    float* hpad;   cudaGetSymbolAddress((void**)&hpad, g_hpad);
    uint32_t* wf1; cudaGetSymbolAddress((void**)&wf1, g_wf1);
    uint32_t* wf2; cudaGetSymbolAddress((void**)&wf2, g_wf2);

    cudaFuncSetAttribute(pacmma, cudaFuncAttributeMaxDynamicSharedMemorySize, SMEM_TOTAL);

    // 1. weights -> pair-interleaved bf16 hi/lo fragments
    prep_wf<<<(2 * KK * 512 + 255) / 256, 256>>>(W1, W2);

    // 2. pad x; zero hpad borders
    pad_x<<<(C * PPLANE + 255) / 256, 256>>>(x);

    // 3. guidance kernel
    dim3 gk(HW / 256, KS);
    compute_k<<<gk, 256>>>(f);

    dim3 gp(KS, H);   // (di, row)

    // 4. layer 1 partials + reduce into hpad interior
    pacmma<<<gp, 128, SMEM_TOTAL>>>(xpad, wf1);
    reduce_part<<<CHW / 256, 256>>>(b1, hpad + PAD * PSTRIDE + PAD, PPLANE, PSTRIDE);

    // 5. layer 2 partials + reduce into out
    pacmma<<<gp, 128, SMEM_TOTAL>>>(hpad, wf2);
    reduce_part<<<CHW / 256, 256>>>(b2, out, HW, W);
}